// round 5
// baseline (speedup 1.0000x reference)
#include <cuda_runtime.h>

// TuckER interaction, restructured:
//   score[n] = h_bn[n]^T * R_p * W[k] * t_bn[n],  k = n>>8, p = n&255, n = 256k+p
// Pass 1: V[n,i] = sum_j W[k][i][j] * t_bn[n][j]        (GEMM per 128-row tile)
// Pass 2: G[k,i]  = sum_d h_bn[256k+p][d] * R_p[d][i];  score = sum_i G[k,i]*V[256k+p][i]

#define NROWS 32768
#define D 128
#define PAD 132
#define BN_EPS 1e-5f

__device__ float g_V[NROWS * D];  // 16 MB scratch (allocation-free rule: static device array)

// ---------------------------------------------------------------------------
// Pass 1: one CTA per 128 rows of t. k = blockIdx>>1 selects W slice.
// C[c][i] = sum_j t_bn[row0+c][j] * W[k][i][j]
// ---------------------------------------------------------------------------
__global__ void __launch_bounds__(256) tucker_pass1(
    const float* __restrict__ t, const float* __restrict__ W,
    const float* __restrict__ gamma1, const float* __restrict__ beta1,
    const float* __restrict__ mean1, const float* __restrict__ var1)
{
    __shared__ float sA[32][PAD];   // t_bn transposed: sA[j'][c]
    __shared__ float sB[32][PAD];   // W transposed:    sB[j'][i]
    __shared__ float sScale[D], sBias[D];

    const int tid  = threadIdx.x;
    const int b    = blockIdx.x;
    const int row0 = b * 128;
    const int k    = b >> 1;
    const float* __restrict__ Wk = W + k * (D * D);

    if (tid < D) {
        float s = gamma1[tid] * rsqrtf(var1[tid] + BN_EPS);
        sScale[tid] = s;
        sBias[tid]  = beta1[tid] - mean1[tid] * s;
    }
    __syncthreads();

    const int tx = tid & 15;    // i-block
    const int ty = tid >> 4;    // c-block
    float acc[8][8];
#pragma unroll
    for (int u = 0; u < 8; u++)
#pragma unroll
        for (int v = 0; v < 8; v++) acc[u][v] = 0.0f;

    for (int jc = 0; jc < D; jc += 32) {
        // cooperative load + transpose of both tiles (128 rows x 32 cols each)
#pragma unroll
        for (int it = 0; it < 4; it++) {
            int idx = tid + it * 256;        // 0..1023
            int c   = idx >> 3;              // 0..127
            int j4  = (idx & 7) * 4;         // 0..28
            int j   = jc + j4;
            float4 tv = *reinterpret_cast<const float4*>(&t[(row0 + c) * D + j]);
            sA[j4 + 0][c] = tv.x * sScale[j + 0] + sBias[j + 0];
            sA[j4 + 1][c] = tv.y * sScale[j + 1] + sBias[j + 1];
            sA[j4 + 2][c] = tv.z * sScale[j + 2] + sBias[j + 2];
            sA[j4 + 3][c] = tv.w * sScale[j + 3] + sBias[j + 3];
            float4 wv = *reinterpret_cast<const float4*>(&Wk[c * D + j]);  // c == i here
            sB[j4 + 0][c] = wv.x;
            sB[j4 + 1][c] = wv.y;
            sB[j4 + 2][c] = wv.z;
            sB[j4 + 3][c] = wv.w;
        }
        __syncthreads();

#pragma unroll
        for (int j = 0; j < 32; j++) {
            float a[8], bb[8];
            *reinterpret_cast<float4*>(a)      = *reinterpret_cast<const float4*>(&sA[j][ty * 8]);
            *reinterpret_cast<float4*>(a + 4)  = *reinterpret_cast<const float4*>(&sA[j][ty * 8 + 4]);
            *reinterpret_cast<float4*>(bb)     = *reinterpret_cast<const float4*>(&sB[j][tx * 8]);
            *reinterpret_cast<float4*>(bb + 4) = *reinterpret_cast<const float4*>(&sB[j][tx * 8 + 4]);
#pragma unroll
            for (int u = 0; u < 8; u++)
#pragma unroll
                for (int v = 0; v < 8; v++)
                    acc[u][v] = fmaf(a[u], bb[v], acc[u][v]);
        }
        __syncthreads();
    }

    // write V tile (coalesced float4)
#pragma unroll
    for (int u = 0; u < 8; u++) {
        int n = row0 + ty * 8 + u;
        float4 o0 = make_float4(acc[u][0], acc[u][1], acc[u][2], acc[u][3]);
        float4 o1 = make_float4(acc[u][4], acc[u][5], acc[u][6], acc[u][7]);
        *reinterpret_cast<float4*>(&g_V[n * D + tx * 8])     = o0;
        *reinterpret_cast<float4*>(&g_V[n * D + tx * 8 + 4]) = o1;
    }
}

// ---------------------------------------------------------------------------
// Pass 2: one CTA per p in [0,256). Rows n = 256k+p, k=0..127.
// G[kk][i] = sum_d h_bn[256*kk+p][d] * R_p[d][i];  out[256*kk+p] = sum_i G*V
// ---------------------------------------------------------------------------
__global__ void __launch_bounds__(256) tucker_pass2(
    const float* __restrict__ h, const float* __restrict__ r,
    const float* __restrict__ gamma0, const float* __restrict__ beta0,
    const float* __restrict__ mean0, const float* __restrict__ var0,
    float* __restrict__ out)
{
    __shared__ float sA[32][PAD];   // h_bn transposed: sA[d'][kk]
    __shared__ float sB[32][PAD];   // R_p natural:     sB[d'][i]
    __shared__ float sScale[D], sBias[D];
    __shared__ float sRed[128][17];

    const int tid = threadIdx.x;
    const int p   = blockIdx.x;
    const float* __restrict__ Rp = r + p * (D * D);

    if (tid < D) {
        float s = gamma0[tid] * rsqrtf(var0[tid] + BN_EPS);
        sScale[tid] = s;
        sBias[tid]  = beta0[tid] - mean0[tid] * s;
    }
    __syncthreads();

    const int tx = tid & 15;    // i-block
    const int ty = tid >> 4;    // kk-block
    float acc[8][8];
#pragma unroll
    for (int u = 0; u < 8; u++)
#pragma unroll
        for (int v = 0; v < 8; v++) acc[u][v] = 0.0f;

    for (int dc = 0; dc < D; dc += 32) {
        // A tile: gather h rows (stride 256 rows), transpose, apply BN
#pragma unroll
        for (int it = 0; it < 4; it++) {
            int idx = tid + it * 256;
            int kk  = idx >> 3;              // 0..127
            int d4  = (idx & 7) * 4;         // 0..28
            int d   = dc + d4;
            float4 hv = *reinterpret_cast<const float4*>(&h[(256 * kk + p) * D + d]);
            sA[d4 + 0][kk] = hv.x * sScale[d + 0] + sBias[d + 0];
            sA[d4 + 1][kk] = hv.y * sScale[d + 1] + sBias[d + 1];
            sA[d4 + 2][kk] = hv.z * sScale[d + 2] + sBias[d + 2];
            sA[d4 + 3][kk] = hv.w * sScale[d + 3] + sBias[d + 3];
        }
        // B tile: R_p rows [dc, dc+32) copied natural layout (already [d][i])
#pragma unroll
        for (int it = 0; it < 4; it++) {
            int idx = tid + it * 256;
            int dd  = idx >> 5;              // 0..31
            int i4  = (idx & 31) * 4;        // 0..124
            float4 rv = *reinterpret_cast<const float4*>(&Rp[(dc + dd) * D + i4]);
            *reinterpret_cast<float4*>(&sB[dd][i4]) = rv;
        }
        __syncthreads();

#pragma unroll
        for (int j = 0; j < 32; j++) {
            float a[8], bb[8];
            *reinterpret_cast<float4*>(a)      = *reinterpret_cast<const float4*>(&sA[j][ty * 8]);
            *reinterpret_cast<float4*>(a + 4)  = *reinterpret_cast<const float4*>(&sA[j][ty * 8 + 4]);
            *reinterpret_cast<float4*>(bb)     = *reinterpret_cast<const float4*>(&sB[j][tx * 8]);
            *reinterpret_cast<float4*>(bb + 4) = *reinterpret_cast<const float4*>(&sB[j][tx * 8 + 4]);
#pragma unroll
            for (int u = 0; u < 8; u++)
#pragma unroll
                for (int v = 0; v < 8; v++)
                    acc[u][v] = fmaf(a[u], bb[v], acc[u][v]);
        }
        __syncthreads();
    }

    // Epilogue: per-row dot with V, then cross-tx reduction
#pragma unroll
    for (int u = 0; u < 8; u++) {
        int kk = ty * 8 + u;
        int n  = 256 * kk + p;
        float4 v0 = *reinterpret_cast<const float4*>(&g_V[n * D + tx * 8]);
        float4 v1 = *reinterpret_cast<const float4*>(&g_V[n * D + tx * 8 + 4]);
        float part = acc[u][0] * v0.x + acc[u][1] * v0.y + acc[u][2] * v0.z + acc[u][3] * v0.w
                   + acc[u][4] * v1.x + acc[u][5] * v1.y + acc[u][6] * v1.z + acc[u][7] * v1.w;
        sRed[kk][tx] = part;
    }
    __syncthreads();

    if (tid < 128) {
        float s = 0.0f;
#pragma unroll
        for (int q = 0; q < 16; q++) s += sRed[tid][q];
        out[256 * tid + p] = s;
    }
}

// ---------------------------------------------------------------------------
// Inputs (metadata order): 0 h, 1 r, 2 t, 3 W, 4 gamma0, 5 beta0, 6 mean0,
//                          7 var0, 8 gamma1, 9 beta1, 10 mean1, 11 var1
// ---------------------------------------------------------------------------
extern "C" void kernel_launch(void* const* d_in, const int* in_sizes, int n_in,
                              void* d_out, int out_size)
{
    const float* h  = (const float*)d_in[0];
    const float* r  = (const float*)d_in[1];
    const float* t  = (const float*)d_in[2];
    const float* W  = (const float*)d_in[3];
    const float* g0 = (const float*)d_in[4];
    const float* b0 = (const float*)d_in[5];
    const float* m0 = (const float*)d_in[6];
    const float* v0 = (const float*)d_in[7];
    const float* g1 = (const float*)d_in[8];
    const float* b1 = (const float*)d_in[9];
    const float* m1 = (const float*)d_in[10];
    const float* v1 = (const float*)d_in[11];
    float* out = (float*)d_out;

    tucker_pass1<<<256, 256>>>(t, W, g1, b1, m1, v1);
    tucker_pass2<<<256, 256>>>(h, r, g0, b0, m0, v0, out);
}